// round 2
// baseline (speedup 1.0000x reference)
#include <cuda_runtime.h>
#include <cooperative_groups.h>

namespace cg = cooperative_groups;

// Problem shapes (fixed by reference setup_inputs)
#define BATCH   256
#define TLEN    64
#define NCTX    2048
#define DDIM    128

// Fusion config: 8-CTA cluster holds one batch's ctx slice in distributed SMEM.
#define CLUSTER 8
#define ROWS    (NCTX / CLUSTER)       // 256 rows per CTA
#define THREADS 512
#define WARPS   (THREADS / 32)         // 16
#define RPW     (ROWS / WARPS)         // 16 rows per warp
#define DYN_SMEM ((ROWS * DDIM + ROWS) * (int)sizeof(float))   // 132 KB

// Fused kernel: one cluster per batch.
//  Phase A: each CTA streams its 256x128 slice from DRAM into SMEM, computing
//           score[n] = TLEN * dot(ctx[n,:], Wc) per row (warp-per-row, float4).
//  Phase B: block max -> DSMEM exchange -> global max; exp+block sum -> DSMEM
//           exchange -> global sum.
//  Phase C: out[n,:] = (exp(score[n]-gmax)/gsum) * SMEM tile  (no 2nd DRAM read).
__global__ void __cluster_dims__(CLUSTER, 1, 1) __launch_bounds__(THREADS, 1)
fused_hop_attention(const float* __restrict__ ctx, const float* __restrict__ W,
                    float* __restrict__ out) {
    cg::cluster_group cluster = cg::this_cluster();
    const int rank = blockIdx.x;          // 0..7  (grid.x == CLUSTER)
    const int b    = blockIdx.y;          // batch
    const int tid  = threadIdx.x;
    const int warp = tid >> 5;
    const int lane = tid & 31;

    extern __shared__ float smem[];
    float4* tile4 = reinterpret_cast<float4*>(smem);   // [ROWS][32] float4
    float*  sc    = smem + ROWS * DDIM;                // [ROWS] scores -> exp
    __shared__ float wred[WARPS];
    __shared__ float stats[2];                         // [0]=local max, [1]=local sum

    // Wc = W[128:256]; each lane holds 4 consecutive weights.
    const float4 wc = reinterpret_cast<const float4*>(W + DDIM)[lane];

    const size_t slice_off = ((size_t)b * NCTX + (size_t)rank * ROWS) * DDIM;
    const float4* src = reinterpret_cast<const float4*>(ctx + slice_off);
    float4*       dst = reinterpret_cast<float4*>(out + slice_off);

    // ---- Phase A: load slice to SMEM + per-row dot (8 loads in flight/thread)
    const int r0 = warp * RPW;
    #pragma unroll
    for (int i = 0; i < RPW; i += 8) {
        float4 v[8];
        #pragma unroll
        for (int j = 0; j < 8; j++)
            v[j] = src[(size_t)(r0 + i + j) * 32 + lane];
        #pragma unroll
        for (int j = 0; j < 8; j++) {
            const int r = r0 + i + j;
            tile4[r * 32 + lane] = v[j];
            float d = v[j].x * wc.x + v[j].y * wc.y + v[j].z * wc.z + v[j].w * wc.w;
            #pragma unroll
            for (int o = 16; o > 0; o >>= 1)
                d += __shfl_xor_sync(0xffffffffu, d, o);
            if (lane == 0) sc[r] = d * (float)TLEN;
        }
    }
    __syncthreads();

    // ---- Phase B1: local max over this CTA's 256 scores
    float m = (tid < ROWS) ? sc[tid] : -3.0e38f;
    #pragma unroll
    for (int o = 16; o > 0; o >>= 1)
        m = fmaxf(m, __shfl_xor_sync(0xffffffffu, m, o));
    if (lane == 0) wred[warp] = m;
    __syncthreads();
    if (warp == 0) {
        float mm = (lane < WARPS) ? wred[lane] : -3.0e38f;
        #pragma unroll
        for (int o = 16; o > 0; o >>= 1)
            mm = fmaxf(mm, __shfl_xor_sync(0xffffffffu, mm, o));
        if (lane == 0) stats[0] = mm;
    }

    // ---- exchange local maxima across the cluster
    cluster.sync();                                   // stats[0] visible everywhere
    float gmax;
    {
        float pm = -3.0e38f;
        if (lane < CLUSTER) {
            const float* ps = cluster.map_shared_rank(stats, lane);
            pm = ps[0];
        }
        #pragma unroll
        for (int o = 4; o > 0; o >>= 1)
            pm = fmaxf(pm, __shfl_xor_sync(0xffffffffu, pm, o));
        gmax = __shfl_sync(0xffffffffu, pm, 0);
    }

    // ---- Phase B2: exp + local sum
    float e = 0.0f;
    if (tid < ROWS) {
        e = expf(sc[tid] - gmax);
        sc[tid] = e;
    }
    #pragma unroll
    for (int o = 16; o > 0; o >>= 1)
        e += __shfl_xor_sync(0xffffffffu, e, o);
    if (lane == 0) wred[warp] = e;
    __syncthreads();
    if (warp == 0) {
        float ss = (lane < WARPS) ? wred[lane] : 0.0f;
        #pragma unroll
        for (int o = 16; o > 0; o >>= 1)
            ss += __shfl_xor_sync(0xffffffffu, ss, o);
        if (lane == 0) stats[1] = ss;
    }

    // ---- exchange local sums across the cluster
    cluster.sync();                                   // stats[1] visible everywhere
    float gsum;
    {
        float psum = 0.0f;
        if (lane < CLUSTER) {
            const float* ps = cluster.map_shared_rank(stats, lane);
            psum = ps[1];
        }
        #pragma unroll
        for (int o = 4; o > 0; o >>= 1)
            psum += __shfl_xor_sync(0xffffffffu, psum, o);
        gsum = __shfl_sync(0xffffffffu, psum, 0);
    }
    const float inv_sum = 1.0f / gsum;

    // All peer DSMEM reads done before any CTA may retire.
    cluster.sync();

    // ---- Phase C: scale SMEM tile and write out (no second DRAM read of ctx)
    #pragma unroll
    for (int i = 0; i < RPW; i++) {
        const int r = r0 + i;
        const float a = sc[r] * inv_sum;              // LDS broadcast
        float4 v = tile4[r * 32 + lane];
        v.x *= a; v.y *= a; v.z *= a; v.w *= a;
        dst[(size_t)r * 32 + lane] = v;
    }
}

extern "C" void kernel_launch(void* const* d_in, const int* in_sizes, int n_in,
                              void* d_out, int out_size) {
    // Inputs: [0] targetsentence_emb (unused: cancels in softmax),
    //         [1] context_emb, [2] W, [3] b (unused: cancels in softmax)
    const float* ctx = (const float*)d_in[1];
    const float* W   = (const float*)d_in[2];
    float* out       = (float*)d_out;

    cudaFuncSetAttribute(fused_hop_attention,
                         cudaFuncAttributeMaxDynamicSharedMemorySize, DYN_SMEM);

    dim3 grid(CLUSTER, BATCH, 1);   // 8 CTAs per cluster, one cluster per batch
    fused_hop_attention<<<grid, THREADS, DYN_SMEM>>>(ctx, W, out);
}

// round 4
// speedup vs baseline: 1.1636x; 1.1636x over previous
#include <cuda_runtime.h>
#include <cooperative_groups.h>

namespace cg = cooperative_groups;

// Problem shapes (fixed by reference setup_inputs)
#define BATCH   256
#define TLEN    64
#define NCTX    2048
#define DDIM    128

// 2-CTA cluster per batch: 148 SMs = 2 x 74 clusters, perfect packing.
#define CLUSTER 2
#define ROWS    (NCTX / CLUSTER)        // 1024 rows per CTA (512 KB slice)
#define THREADS 512
#define WARPS   (THREADS / 32)          // 16
#define RPW     (ROWS / WARPS)          // 64 rows per warp

__global__ void __cluster_dims__(CLUSTER, 1, 1) __launch_bounds__(THREADS, 2)
fused_hop_attention(const float* __restrict__ ctx, const float* __restrict__ W,
                    float* __restrict__ out) {
    cg::cluster_group cluster = cg::this_cluster();
    const int rank = blockIdx.x;        // 0..1
    const int b    = blockIdx.y;        // batch
    const int tid  = threadIdx.x;
    const int warp = tid >> 5;
    const int lane = tid & 31;

    __shared__ float sc[ROWS];          // scores -> attention weights (4 KB)
    __shared__ float wred[WARPS];
    __shared__ __align__(8) float stats[2];   // [0]=local max, [1]=local sum

    // Wc = W[128:256]; each lane holds 4 consecutive weights.
    const float4 wc = reinterpret_cast<const float4*>(W + DDIM)[lane];

    const size_t off = ((size_t)b * NCTX + (size_t)rank * ROWS) * DDIM;
    const float4* src = reinterpret_cast<const float4*>(ctx + off);
    float4*       dst = reinterpret_cast<float4*>(out + off);

    const int r0 = warp * RPW;

    // ---- Phase 1: stream slice, per-row dot (8 independent LDG.128/thread).
    #pragma unroll 2
    for (int i = 0; i < RPW; i += 8) {
        float4 v[8];
        #pragma unroll
        for (int j = 0; j < 8; j++)
            v[j] = src[(size_t)(r0 + i + j) * 32 + lane];
        #pragma unroll
        for (int j = 0; j < 8; j++) {
            float d = v[j].x * wc.x + v[j].y * wc.y + v[j].z * wc.z + v[j].w * wc.w;
            #pragma unroll
            for (int o = 16; o > 0; o >>= 1)
                d += __shfl_xor_sync(0xffffffffu, d, o);
            if (lane == 0) sc[r0 + i + j] = d * (float)TLEN;
        }
    }
    __syncthreads();

    // ---- Local max over 1024 scores (2 per thread).
    float m = fmaxf(sc[tid], sc[tid + THREADS]);
    #pragma unroll
    for (int o = 16; o > 0; o >>= 1)
        m = fmaxf(m, __shfl_xor_sync(0xffffffffu, m, o));
    if (lane == 0) wred[warp] = m;
    __syncthreads();
    if (warp == 0) {
        float mm = (lane < WARPS) ? wred[lane] : -3.0e38f;
        #pragma unroll
        for (int o = 8; o > 0; o >>= 1)
            mm = fmaxf(mm, __shfl_xor_sync(0xffffffffu, mm, o));
        if (lane == 0) stats[0] = mm;
    }
    __syncthreads();
    const float lmax = stats[0];

    // ---- Local sum of exp(s - lmax).
    float e = __expf(sc[tid] - lmax) + __expf(sc[tid + THREADS] - lmax);
    #pragma unroll
    for (int o = 16; o > 0; o >>= 1)
        e += __shfl_xor_sync(0xffffffffu, e, o);
    if (lane == 0) wred[warp] = e;
    __syncthreads();
    if (warp == 0) {
        float ss = (lane < WARPS) ? wred[lane] : 0.0f;
        #pragma unroll
        for (int o = 8; o > 0; o >>= 1)
            ss += __shfl_xor_sync(0xffffffffu, ss, o);
        if (lane == 0) stats[1] = ss;
    }

    // ---- Exchange (lmax, lsum) with the single peer CTA; online combine.
    cluster.sync();   // stats visible cluster-wide; all threads past local phase
    const float lsum = stats[1];
    const float2 ps = *reinterpret_cast<const float2*>(
        cluster.map_shared_rank((const void*)stats, rank ^ 1));
    const float gmax = fmaxf(lmax, ps.x);
    const float gsum = lsum * __expf(lmax - gmax) + ps.y * __expf(ps.x - gmax);
    const float inv_sum = 1.0f / gsum;

    // ---- Scores -> attention weights in smem.
    sc[tid]           = __expf(sc[tid] - gmax) * inv_sum;
    sc[tid + THREADS] = __expf(sc[tid + THREADS] - gmax) * inv_sum;
    __syncthreads();

    // ---- Phase 2: re-read slice (L2-resident), scale, streaming store.
    #pragma unroll 2
    for (int i = 0; i < RPW; i += 8) {
        float4 v[8];
        #pragma unroll
        for (int j = 0; j < 8; j++)
            v[j] = __ldcs(&src[(size_t)(r0 + i + j) * 32 + lane]);
        #pragma unroll
        for (int j = 0; j < 8; j++) {
            const float a = sc[r0 + i + j];
            v[j].x *= a; v[j].y *= a; v[j].z *= a; v[j].w *= a;
            __stcs(&dst[(size_t)(r0 + i + j) * 32 + lane], v[j]);
        }
    }

    // No CTA may exit while its peer can still read its DSMEM stats.
    cluster.sync();
}

extern "C" void kernel_launch(void* const* d_in, const int* in_sizes, int n_in,
                              void* d_out, int out_size) {
    // Inputs: [0] target_emb (cancels in softmax), [1] context_emb, [2] W,
    //         [3] b (cancels in softmax)
    const float* ctx = (const float*)d_in[1];
    const float* W   = (const float*)d_in[2];
    float* out       = (float*)d_out;

    dim3 grid(CLUSTER, BATCH, 1);
    fused_hop_attention<<<grid, THREADS>>>(ctx, W, out);
}